// round 1
// baseline (speedup 1.0000x reference)
#include <cuda_runtime.h>
#include <cuda_bf16.h>
#include <math.h>

// Problem constants
#define NROW 384          // N = 2*bs
#define BSZ  192
#define DIM  1024
#define NM1  383          // N-1
// M = N*(N-1)^2
#define MDEN 56328576.0

// Scratch (device globals; no allocation allowed)
__device__ float g_sq[NROW];
__device__ float g_z[NROW * NROW];
__device__ float g_row[NROW];

__device__ __forceinline__ const float* frow(const float* f, int r) {
    // feats row r: r<192 -> features[r,0,:]; else features[r-192,1,:]
    return f + (r < BSZ ? r * (2 * DIM) : (r - BSZ) * (2 * DIM) + DIM);
}

// ---------------------------------------------------------------------------
// Kernel 1: squared norms per row
// ---------------------------------------------------------------------------
__global__ __launch_bounds__(256) void prep_kernel(const float* __restrict__ feats) {
    __shared__ float red[256];
    int i = blockIdx.x;
    const float* row = frow(feats, i);
    float s = 0.f;
    #pragma unroll
    for (int k = threadIdx.x; k < DIM; k += 256) {
        float v = row[k];
        s = fmaf(v, v, s);
    }
    red[threadIdx.x] = s;
    __syncthreads();
    #pragma unroll
    for (int st = 128; st > 0; st >>= 1) {
        if (threadIdx.x < st) red[threadIdx.x] += red[threadIdx.x + st];
        __syncthreads();
    }
    if (threadIdx.x == 0) g_sq[i] = red[0];
}

// ---------------------------------------------------------------------------
// Kernel 2: Gram -> pairwise L2 distances  z[i][j] = sqrt(max(si+sj-2*dot,0))
// 32x32 output tile per block, grid 12x12 = 144 blocks (one wave)
// ---------------------------------------------------------------------------
__global__ __launch_bounds__(256) void gram_kernel(const float* __restrict__ feats) {
    __shared__ float As[32][32];   // [k][row]
    __shared__ float Bs[32][32];   // [k][col]
    int tid = threadIdx.x;
    int r0 = blockIdx.y * 32, c0 = blockIdx.x * 32;
    int lr = tid & 31;     // row-in-tile for loads
    int kq = tid >> 5;     // 0..7 -> k-quad
    const float* arow = frow(feats, r0 + lr);
    const float* brow = frow(feats, c0 + lr);
    int ty = tid >> 4, tx = tid & 15;   // compute layout: 2x2 micro-tile
    float c00 = 0.f, c01 = 0.f, c10 = 0.f, c11 = 0.f;

    for (int k0 = 0; k0 < DIM; k0 += 32) {
        float4 av = *(const float4*)(arow + k0 + kq * 4);
        float4 bv = *(const float4*)(brow + k0 + kq * 4);
        As[kq * 4 + 0][lr] = av.x; As[kq * 4 + 1][lr] = av.y;
        As[kq * 4 + 2][lr] = av.z; As[kq * 4 + 3][lr] = av.w;
        Bs[kq * 4 + 0][lr] = bv.x; Bs[kq * 4 + 1][lr] = bv.y;
        Bs[kq * 4 + 2][lr] = bv.z; Bs[kq * 4 + 3][lr] = bv.w;
        __syncthreads();
        #pragma unroll
        for (int kk = 0; kk < 32; kk++) {
            float2 a = *(const float2*)&As[kk][2 * ty];
            float2 b = *(const float2*)&Bs[kk][2 * tx];
            c00 = fmaf(a.x, b.x, c00);
            c01 = fmaf(a.x, b.y, c01);
            c10 = fmaf(a.y, b.x, c10);
            c11 = fmaf(a.y, b.y, c11);
        }
        __syncthreads();
    }
    int r = r0 + 2 * ty, c = c0 + 2 * tx;
    float sr0 = g_sq[r], sr1 = g_sq[r + 1], sc0 = g_sq[c], sc1 = g_sq[c + 1];
    g_z[r * NROW + c]           = sqrtf(fmaxf(sr0 + sc0 - 2.f * c00, 0.f));
    g_z[r * NROW + c + 1]       = sqrtf(fmaxf(sr0 + sc1 - 2.f * c01, 0.f));
    g_z[(r + 1) * NROW + c]     = sqrtf(fmaxf(sr1 + sc0 - 2.f * c10, 0.f));
    g_z[(r + 1) * NROW + c + 1] = sqrtf(fmaxf(sr1 + sc1 - 2.f * c11, 0.f));
}

// ---------------------------------------------------------------------------
// Kernel 3: per-row loss pieces.
// Per row i (block): build compacted off-diag arrays z,b (b = 0.1*dense_rank),
// counting-sort by label-diff (deterministic stable order), then:
//   rowsum = 2n*(Var-sums of z and b) - 2*Sum|dz*db| + Sum_pos d*sigmoid(d-0.1)
//            - Sum_pos d^2
// ---------------------------------------------------------------------------
__device__ __forceinline__ float2 block_reduce2(float2 v, float2* red, int tid) {
    red[tid] = v;
    __syncthreads();
    #pragma unroll
    for (int s = 192; s >= 6; s >>= 1) {
        if (tid < s) {
            red[tid].x += red[tid + s].x;
            red[tid].y += red[tid + s].y;
        }
        __syncthreads();
    }
    if (tid == 0) {
        float2 r = red[0];
        #pragma unroll
        for (int q = 1; q < 6; q++) { r.x += red[q].x; r.y += red[q].y; }
        red[0] = r;
    }
    __syncthreads();
    float2 out = red[0];
    __syncthreads();
    return out;
}

__global__ __launch_bounds__(384) void row_kernel(const int* __restrict__ labels) {
    __shared__ float2 zb[NROW];                 // sorted (z, b)
    __shared__ short  gsA[NROW], geA[NROW];     // group bounds per sorted pos
    __shared__ int    cntw[12][52];             // per-warp label-diff histogram
    __shared__ int    tot[52];
    __shared__ int    basev[53];
    __shared__ unsigned long long ymask;
    __shared__ float2 red2[NROW];

    int tid = threadIdx.x;
    int i = blockIdx.x;
    int lane = tid & 31, wid = tid >> 5;
    bool valid = tid < NM1;

    // zero per-warp histograms + mask
    {
        int* cw = &cntw[0][0];
        for (int idx = tid; idx < 12 * 52; idx += 384) cw[idx] = 0;
        if (tid == 0) ymask = 0ull;
    }
    __syncthreads();

    int labi = labels[i >= BSZ ? i - BSZ : i];
    int yp = 0;
    float zp = 0.f;
    if (valid) {
        int j = tid + (tid >= i);
        zp = g_z[i * NROW + j];
        int labj = labels[j >= BSZ ? j - BSZ : j];
        yp = abs(labi - labj);                    // 0..49
        atomicOr(&ymask, 1ull << yp);
        atomicAdd(&cntw[wid][yp], 1);
    }
    __syncthreads();

    // dense rank via presence-bitmask popcount; b = 0.1*rank
    float bp = 0.1f * (float)__popcll(ymask & ((1ull << yp) - 1ull));

    // bin totals + exclusive scan
    if (tid < 52) {
        int s = 0;
        #pragma unroll
        for (int w2 = 0; w2 < 12; w2++) s += cntw[w2][tid];
        tot[tid] = s;
    }
    __syncthreads();
    if (tid == 0) {
        int run = 0;
        for (int v = 0; v < 52; v++) { basev[v] = run; run += tot[v]; }
        basev[52] = run;
    }
    __syncthreads();

    // deterministic stable position: bin base + earlier-warp count + within-warp rank
    unsigned mm = __match_any_sync(0xffffffffu, yp);
    int within = __popc(mm & ((1u << lane) - 1u));
    int before = 0;
    #pragma unroll
    for (int w2 = 0; w2 < 12; w2++)
        if (w2 < wid) before += cntw[w2][yp];
    if (valid) {
        int pos = basev[yp] + before + within;
        zb[pos] = make_float2(zp, bp);
        gsA[pos] = (short)basev[yp];
        geA[pos] = (short)(basev[yp] + tot[yp]);
    }
    __syncthreads();

    // closed-form variance sums (centered for fp32 safety)
    float2 s1 = block_reduce2(make_float2(valid ? zp : 0.f, valid ? bp : 0.f), red2, tid);
    float zm = s1.x * (1.0f / (float)NM1);
    float bm = s1.y * (1.0f / (float)NM1);
    float dzc = zp - zm, dbc = bp - bm;
    float2 s2 = block_reduce2(make_float2(valid ? dzc * dzc : 0.f,
                                          valid ? dbc * dbc : 0.f), red2, tid);

    // cross term: each thread owns one sorted j, loops all k (broadcast LDS)
    float zj = 0.f, bj = 0.f;
    if (valid) { float2 t = zb[tid]; zj = t.x; bj = t.y; }
    float accC = 0.f;
    #pragma unroll 8
    for (int k = 0; k < NM1; k++) {
        float2 t = zb[k];
        accC += fabsf((t.x - zj) * (t.y - bj));
    }

    // pos correction: same-y pairs are the sorted group of j
    float accP = 0.f, accQ = 0.f;
    if (valid) {
        int g0 = gsA[tid], g1 = geA[tid];
        for (int kk = g0; kk < g1; kk++) {
            float d = fabsf(zb[kk].x - zj);
            accP += __fdividef(d, 1.0f + __expf(0.1f - d));
            accQ = fmaf(d, d, accQ);
        }
    }

    float2 s3 = block_reduce2(make_float2(valid ? accC : 0.f, accP), red2, tid);
    float2 s4 = block_reduce2(make_float2(accQ, 0.f), red2, tid);

    if (tid == 0) {
        // 2n * (S2z + S2b) - 2*C + P - Q   (n = 383)
        float total = (2.0f * (float)NM1) * (s2.x + s2.y)
                    - 2.0f * s3.x + s3.y - s4.x;
        g_row[i] = total;
    }
}

// ---------------------------------------------------------------------------
// Kernel 4: deterministic final reduction (double accumulation)
// ---------------------------------------------------------------------------
__global__ __launch_bounds__(128) void final_kernel(float* __restrict__ out) {
    __shared__ double red[128];
    int t = threadIdx.x;
    double s = (double)g_row[t] + (double)g_row[t + 128] + (double)g_row[t + 256];
    red[t] = s;
    __syncthreads();
    #pragma unroll
    for (int st = 64; st > 0; st >>= 1) {
        if (t < st) red[t] += red[t + st];
        __syncthreads();
    }
    if (t == 0) out[0] = (float)(red[0] / MDEN);
}

// ---------------------------------------------------------------------------
extern "C" void kernel_launch(void* const* d_in, const int* in_sizes, int n_in,
                              void* d_out, int out_size) {
    const float* features = (const float*)d_in[0];   // [192, 2, 1024] f32
    const int*   labels   = (const int*)d_in[1];     // [192, 1] i32
    (void)in_sizes; (void)n_in; (void)out_size;      // d_in[2] (ranks) unused

    prep_kernel<<<NROW, 256>>>(features);
    gram_kernel<<<dim3(12, 12), 256>>>(features);
    row_kernel<<<NROW, 384>>>(labels);
    final_kernel<<<1, 128>>>((float*)d_out);
}